// round 6
// baseline (speedup 1.0000x reference)
#include <cuda_runtime.h>
#include <math.h>

// Fully fused TreeLSTM cell, register-tiled SGEMM with f32x2 FMA.
// CTA tile: 128 rows x 128 cols, 256 threads, 8x8 microtile per thread.
// A (emb, h_iou) stored k-major in smem; LN done in registers via shuffles.

#define TM      128
#define THREADS 256
#define AS      132          // k-major row stride (floats): 132%32=4, 16B-aligned
#define BK      16

// smem layout (floats)
#define OFF_EMB 0                         // [128 k][AS]  (r in 0..127)
#define OFF_HIO (128 * AS)                // [256 k][AS]
#define OFF_B   (OFF_HIO + 256 * AS)      // double buffer [2][BK][128]
#define OFF_NT  (OFF_B + 2 * BK * 128)    // 512 ints
#define SMEM_FLOATS (OFF_NT + 512)        // 55296
#define SMEM_BYTES  (SMEM_FLOATS * 4)     // 221184

typedef unsigned long long u64;

__device__ __forceinline__ u64 pack2(float lo, float hi)
{
    u64 r;
    asm("mov.b64 %0, {%1, %2};" : "=l"(r)
        : "r"(__float_as_uint(lo)), "r"(__float_as_uint(hi)));
    return r;
}
__device__ __forceinline__ u64 pack_dup(float v)
{
    u64 r;
    unsigned int u = __float_as_uint(v);
    asm("mov.b64 %0, {%1, %1};" : "=l"(r) : "r"(u));
    return r;
}
__device__ __forceinline__ void unpack2(u64 v, float& lo, float& hi)
{
    unsigned int a, b;
    asm("mov.b64 {%0, %1}, %2;" : "=r"(a), "=r"(b) : "l"(v));
    lo = __uint_as_float(a);
    hi = __uint_as_float(b);
}
__device__ __forceinline__ void fma2(u64& d, u64 a, u64 b)
{
    asm("fma.rn.f32x2 %0, %1, %2, %0;" : "+l"(d) : "l"(a), "l"(b));
}

__device__ __forceinline__ float sigm(float x) { return 1.f / (1.f + expf(-x)); }

// One GEMM source: acc += sA(k-major)[K x 128rows] ^T @ W[128c x K]^T slice.
// Double-buffered sB, one __syncthreads per chunk.
__device__ __forceinline__ void gemm_src(
    u64 acc[8][4],
    const float* __restrict__ Wsrc, int ldw, int K,
    const float* sA, float* sB, int tid, int tx8, int ty8)
{
    const int c  = tid >> 1;
    const int kh = (tid & 1) * 8;
    const float* wp = Wsrc + (size_t)c * ldw + kh;

    float4 p0 = __ldg((const float4*)wp);
    float4 p1 = __ldg((const float4*)(wp + 4));
    const int nch = K / BK;

    for (int ch = 0; ch < nch; ch++) {
        float* b = sB + (ch & 1) * (BK * 128);
        b[(kh + 0) * 128 + c] = p0.x;
        b[(kh + 1) * 128 + c] = p0.y;
        b[(kh + 2) * 128 + c] = p0.z;
        b[(kh + 3) * 128 + c] = p0.w;
        b[(kh + 4) * 128 + c] = p1.x;
        b[(kh + 5) * 128 + c] = p1.y;
        b[(kh + 6) * 128 + c] = p1.z;
        b[(kh + 7) * 128 + c] = p1.w;
        if (ch + 1 < nch) {
            p0 = __ldg((const float4*)(wp + (ch + 1) * BK));
            p1 = __ldg((const float4*)(wp + (ch + 1) * BK + 4));
        }
        __syncthreads();
        const float* a = sA + ch * BK * AS;
#pragma unroll
        for (int kk = 0; kk < BK; kk++) {
            float4 a0 = *(const float4*)(a + kk * AS + ty8);
            float4 a1 = *(const float4*)(a + kk * AS + ty8 + 4);
            float4 b0 = *(const float4*)(b + kk * 128 + tx8);
            float4 b1 = *(const float4*)(b + kk * 128 + tx8 + 4);
            u64 pb[4];
            pb[0] = pack2(b0.x, b0.y);
            pb[1] = pack2(b0.z, b0.w);
            pb[2] = pack2(b1.x, b1.y);
            pb[3] = pack2(b1.z, b1.w);
            u64 pa[8];
            pa[0] = pack_dup(a0.x); pa[1] = pack_dup(a0.y);
            pa[2] = pack_dup(a0.z); pa[3] = pack_dup(a0.w);
            pa[4] = pack_dup(a1.x); pa[5] = pack_dup(a1.y);
            pa[6] = pack_dup(a1.z); pa[7] = pack_dup(a1.w);
#pragma unroll
            for (int i = 0; i < 8; i++)
#pragma unroll
                for (int j = 0; j < 4; j++)
                    fma2(acc[i][j], pa[i], pb[j]);
        }
        // no trailing sync: next STS targets the other buffer, and every warp
        // reaching it has passed this chunk's sync (so prior compute on that
        // buffer is globally complete).
    }
}

// In-register LayerNorm over 128 cols: half-warp (16 lanes) holds 8 full rows,
// each lane 8 cols (tx8..tx8+7). xor-shuffle 1,2,4,8 reduces within half-warp.
__device__ __forceinline__ void ln_x(float x[8][8],
                                     const float* __restrict__ g,
                                     const float* __restrict__ b, int tx8)
{
    float4 g0 = __ldg((const float4*)(g + tx8));
    float4 g1 = __ldg((const float4*)(g + tx8 + 4));
    float4 b0 = __ldg((const float4*)(b + tx8));
    float4 b1 = __ldg((const float4*)(b + tx8 + 4));
    float gg[8] = { g0.x, g0.y, g0.z, g0.w, g1.x, g1.y, g1.z, g1.w };
    float bb[8] = { b0.x, b0.y, b0.z, b0.w, b1.x, b1.y, b1.z, b1.w };
#pragma unroll
    for (int i = 0; i < 8; i++) {
        float s = x[i][0] + x[i][1] + x[i][2] + x[i][3]
                + x[i][4] + x[i][5] + x[i][6] + x[i][7];
#pragma unroll
        for (int o = 1; o < 16; o <<= 1) s += __shfl_xor_sync(0xffffffffu, s, o);
        float mu = s * 0.0078125f;
        float q = 0.f;
#pragma unroll
        for (int j = 0; j < 8; j++) {
            x[i][j] -= mu;
            q += x[i][j] * x[i][j];
        }
#pragma unroll
        for (int o = 1; o < 16; o <<= 1) q += __shfl_xor_sync(0xffffffffu, q, o);
        float rs = rsqrtf(q * 0.0078125f + 1e-5f);
#pragma unroll
        for (int j = 0; j < 8; j++)
            x[i][j] = x[i][j] * rs * gg[j] + bb[j];
    }
}

__global__ __launch_bounds__(THREADS) void treelstm_fused(
    const float* __restrict__ emb,
    const float* __restrict__ h_child,
    const float* __restrict__ c_child,
    const int*   __restrict__ n_type,
    const float* __restrict__ W_iou,
    const float* __restrict__ U_iou,
    const float* __restrict__ b_iou,
    const float* __restrict__ W_f,
    const float* __restrict__ U_f,
    const float* __restrict__ b_f,
    const float* __restrict__ g_i,  const float* __restrict__ b_i,
    const float* __restrict__ g_o,  const float* __restrict__ b_o,
    const float* __restrict__ g_u,  const float* __restrict__ b_u,
    const float* __restrict__ gn_f, const float* __restrict__ bn_f,
    const float* __restrict__ gn_c, const float* __restrict__ bn_c,
    float* __restrict__ out, int n)
{
    extern __shared__ float sm[];
    float* sEmb = sm + OFF_EMB;
    float* sHio = sm + OFF_HIO;
    float* sB   = sm + OFF_B;
    int*   sNT  = (int*)(sm + OFF_NT);

    const int tid  = threadIdx.x;
    const int tx8  = (tid & 15) * 8;
    const int ty8  = (tid >> 4) * 8;
    const int row0 = blockIdx.x * TM;

    // ---- Phase 0: n_type, emb (transposed to k-major), typed h aggregation ----
    for (int e = tid; e < 512; e += THREADS)
        sNT[e] = n_type[row0 * 4 + e];

    for (int e = tid; e < 128 * 32; e += THREADS) {     // 32 float4 per row
        int r = e >> 5, k4 = (e & 31) * 4;
        float4 v = __ldg((const float4*)(emb + (size_t)(row0 + r) * 128 + k4));
        sEmb[(k4 + 0) * AS + r] = v.x;
        sEmb[(k4 + 1) * AS + r] = v.y;
        sEmb[(k4 + 2) * AS + r] = v.z;
        sEmb[(k4 + 3) * AS + r] = v.w;
    }
    __syncthreads();   // sNT ready for aggregation

    for (int e = tid; e < 128 * 128; e += THREADS) {
        int c = e & 127, r = e >> 7;
        const float* hp = h_child + ((size_t)(row0 + r) * 4) * 128 + c;
        float h0 = 0.f, h1 = 0.f;
#pragma unroll
        for (int k = 0; k < 4; k++) {
            float h = __ldg(hp + k * 128);
            if (sNT[r * 4 + k] == 0) h0 += h; else h1 += h;
        }
        sHio[c * AS + r]         = h0;
        sHio[(c + 128) * AS + r] = h1;
    }
    __syncthreads();

    u64 acc[8][4];
    float x[8][8];
    float cR[8][8];

#define ZERO_ACC()                                          \
    _Pragma("unroll") for (int i = 0; i < 8; i++)           \
    _Pragma("unroll") for (int j = 0; j < 4; j++) acc[i][j] = 0ull;

#define UNPACK_BIAS(BPTR)                                                  \
    {                                                                      \
        float4 v0 = __ldg((const float4*)((BPTR) + tx8));                  \
        float4 v1 = __ldg((const float4*)((BPTR) + tx8 + 4));              \
        float bv[8] = { v0.x, v0.y, v0.z, v0.w, v1.x, v1.y, v1.z, v1.w };  \
        _Pragma("unroll") for (int i = 0; i < 8; i++) {                    \
            _Pragma("unroll") for (int jp = 0; jp < 4; jp++)               \
                unpack2(acc[i][jp], x[i][2 * jp], x[i][2 * jp + 1]);       \
            _Pragma("unroll") for (int j = 0; j < 8; j++)                  \
                x[i][j] += bv[j];                                          \
        }                                                                  \
    }

    // ================= Stage u =================
    ZERO_ACC();
    gemm_src(acc, W_iou + 256 * 128, 128, 128, sEmb, sB, tid, tx8, ty8);
    gemm_src(acc, U_iou + 256 * 256, 256, 256, sHio, sB, tid, tx8, ty8);
    UNPACK_BIAS(b_iou + 256);
    ln_x(x, g_u, b_u, tx8);
#pragma unroll
    for (int i = 0; i < 8; i++)
#pragma unroll
        for (int j = 0; j < 8; j++) cR[i][j] = tanhf(x[i][j]);

    // ================= Stage i: cR = sigm(i) * tanh(u) =================
    ZERO_ACC();
    gemm_src(acc, W_iou, 128, 128, sEmb, sB, tid, tx8, ty8);
    gemm_src(acc, U_iou, 256, 256, sHio, sB, tid, tx8, ty8);
    UNPACK_BIAS(b_iou);
    ln_x(x, g_i, b_i, tx8);
#pragma unroll
    for (int i = 0; i < 8; i++)
#pragma unroll
        for (int j = 0; j < 8; j++) cR[i][j] *= sigm(x[i][j]);

    // ================= Stage f0: cR += F0 * ct0 =================
    ZERO_ACC();
    gemm_src(acc, W_f, 128, 128, sEmb, sB, tid, tx8, ty8);
    gemm_src(acc, U_f, 256, 256, sHio, sB, tid, tx8, ty8);
    UNPACK_BIAS(b_f);
    ln_x(x, gn_f, bn_f, tx8);
#pragma unroll
    for (int i = 0; i < 8; i++) {
        const float* cc = c_child + ((size_t)(row0 + ty8 + i) * 4) * 128 + tx8;
        float ct[8] = { 0.f, 0.f, 0.f, 0.f, 0.f, 0.f, 0.f, 0.f };
#pragma unroll
        for (int k = 0; k < 4; k++) {
            if (sNT[(ty8 + i) * 4 + k] == 0) {
                float4 v0 = __ldg((const float4*)(cc + k * 128));
                float4 v1 = __ldg((const float4*)(cc + k * 128 + 4));
                ct[0] += v0.x; ct[1] += v0.y; ct[2] += v0.z; ct[3] += v0.w;
                ct[4] += v1.x; ct[5] += v1.y; ct[6] += v1.z; ct[7] += v1.w;
            }
        }
#pragma unroll
        for (int j = 0; j < 8; j++) cR[i][j] += sigm(x[i][j]) * ct[j];
    }

    // ================= Stage f1: cR += F1 * ct1 =================
    ZERO_ACC();
    gemm_src(acc, W_f, 128, 128, sEmb, sB, tid, tx8, ty8);
    gemm_src(acc, U_f + 128 * 256, 256, 256, sHio, sB, tid, tx8, ty8);
    UNPACK_BIAS(b_f);
    ln_x(x, gn_f, bn_f, tx8);
#pragma unroll
    for (int i = 0; i < 8; i++) {
        const float* cc = c_child + ((size_t)(row0 + ty8 + i) * 4) * 128 + tx8;
        float ct[8] = { 0.f, 0.f, 0.f, 0.f, 0.f, 0.f, 0.f, 0.f };
#pragma unroll
        for (int k = 0; k < 4; k++) {
            if (sNT[(ty8 + i) * 4 + k] == 1) {
                float4 v0 = __ldg((const float4*)(cc + k * 128));
                float4 v1 = __ldg((const float4*)(cc + k * 128 + 4));
                ct[0] += v0.x; ct[1] += v0.y; ct[2] += v0.z; ct[3] += v0.w;
                ct[4] += v1.x; ct[5] += v1.y; ct[6] += v1.z; ct[7] += v1.w;
            }
        }
#pragma unroll
        for (int j = 0; j < 8; j++) cR[i][j] += sigm(x[i][j]) * ct[j];
    }

    // ======= write c, then cR := tanh(LN(c)) =======
#pragma unroll
    for (int i = 0; i < 8; i++) {
        float* oc = out + (size_t)n * 128 + (size_t)(row0 + ty8 + i) * 128 + tx8;
        *(float4*)oc       = make_float4(cR[i][0], cR[i][1], cR[i][2], cR[i][3]);
        *(float4*)(oc + 4) = make_float4(cR[i][4], cR[i][5], cR[i][6], cR[i][7]);
#pragma unroll
        for (int j = 0; j < 8; j++) x[i][j] = cR[i][j];
    }
    ln_x(x, gn_c, bn_c, tx8);
#pragma unroll
    for (int i = 0; i < 8; i++)
#pragma unroll
        for (int j = 0; j < 8; j++) cR[i][j] = tanhf(x[i][j]);

    // ================= Stage o: h = sigm(o) * tanh(LN(c)) =================
    ZERO_ACC();
    gemm_src(acc, W_iou + 128 * 128, 128, 128, sEmb, sB, tid, tx8, ty8);
    gemm_src(acc, U_iou + 128 * 256, 256, 256, sHio, sB, tid, tx8, ty8);
    UNPACK_BIAS(b_iou + 128);
    ln_x(x, g_o, b_o, tx8);
#pragma unroll
    for (int i = 0; i < 8; i++) {
        float h[8];
#pragma unroll
        for (int j = 0; j < 8; j++) h[j] = sigm(x[i][j]) * cR[i][j];
        float* oh = out + (size_t)(row0 + ty8 + i) * 128 + tx8;
        *(float4*)oh       = make_float4(h[0], h[1], h[2], h[3]);
        *(float4*)(oh + 4) = make_float4(h[4], h[5], h[6], h[7]);
    }
}

extern "C" void kernel_launch(void* const* d_in, const int* in_sizes, int n_in,
                              void* d_out, int out_size)
{
    const float* emb     = (const float*)d_in[0];
    const float* h_child = (const float*)d_in[1];
    const float* c_child = (const float*)d_in[2];
    const int*   n_type  = (const int*)  d_in[3];
    const float* W_iou   = (const float*)d_in[4];
    const float* U_iou   = (const float*)d_in[5];
    const float* b_iou   = (const float*)d_in[6];
    const float* W_f     = (const float*)d_in[7];
    const float* U_f     = (const float*)d_in[8];
    const float* b_f     = (const float*)d_in[9];
    const float* g_i  = (const float*)d_in[10];
    const float* b_i  = (const float*)d_in[11];
    const float* g_o  = (const float*)d_in[12];
    const float* b_o  = (const float*)d_in[13];
    const float* g_u  = (const float*)d_in[14];
    const float* b_u  = (const float*)d_in[15];
    const float* gn_f = (const float*)d_in[16];
    const float* bn_f = (const float*)d_in[17];
    const float* gn_c = (const float*)d_in[18];
    const float* bn_c = (const float*)d_in[19];
    float* out = (float*)d_out;

    int n = in_sizes[0] / 128;   // N = 131072 (multiple of 128)

    static int smem_set = 0;
    if (!smem_set) {
        cudaFuncSetAttribute(treelstm_fused,
                             cudaFuncAttributeMaxDynamicSharedMemorySize,
                             SMEM_BYTES);
        smem_set = 1;
    }

    treelstm_fused<<<n / TM, THREADS, SMEM_BYTES>>>(
        emb, h_child, c_child, n_type, W_iou, U_iou, b_iou, W_f, U_f, b_f,
        g_i, b_i, g_o, b_o, g_u, b_u, gn_f, bn_f, gn_c, bn_c, out, n);
}

// round 11
// speedup vs baseline: 1.6204x; 1.6204x over previous
#include <cuda_runtime.h>
#include <math.h>
#include <stdint.h>

// Fused TreeLSTM cell using tf32 mma.sync (m16n8k8) tensor cores.
// CTA = 128 rows, 256 threads (8 warps x 16 rows x 128 cols).
// A=[emb|ht0|ht1] tf32 row-major in smem; weights fragment-packed, dbl-buffered.
// Output columns permuted so each thread owns a contiguous 32-col logical block.

#define AS 388                       // A row stride in words (384 + 4 pad)
#define B_WORDS 4096                 // one 32k x 128c chunk, packed
#define SMEM_WORDS (128 * AS + 2 * B_WORDS)
#define SMEM_BYTES (SMEM_WORDS * 4)  // 231424 <= 232448

__device__ __forceinline__ uint32_t tf32r(float x) {
    uint32_t r; asm("cvt.rna.tf32.f32 %0, %1;" : "=r"(r) : "f"(x)); return r;
}
__device__ __forceinline__ void mma8(float d[4], uint32_t a0, uint32_t a1,
                                     uint32_t a2, uint32_t a3,
                                     uint32_t b0, uint32_t b1)
{
    asm volatile(
        "mma.sync.aligned.m16n8k8.row.col.f32.tf32.tf32.f32 "
        "{%0,%1,%2,%3}, {%4,%5,%6,%7}, {%8,%9}, {%0,%1,%2,%3};"
        : "+f"(d[0]), "+f"(d[1]), "+f"(d[2]), "+f"(d[3])
        : "r"(a0), "r"(a1), "r"(a2), "r"(a3), "r"(b0), "r"(b1));
}
__device__ __forceinline__ float sigm(float x) { return 1.f / (1.f + expf(-x)); }
__device__ __forceinline__ void quadred(float& v)
{
    v += __shfl_xor_sync(0xffffffffu, v, 1);
    v += __shfl_xor_sync(0xffffffffu, v, 2);
}

// LayerNorm over a 128-col row held by a lane quad (32 cols per lane, logical
// cols lb..lb+31). In-place; gamma/beta indexed at logical cols.
__device__ __forceinline__ void ln32(float x[32], const float* __restrict__ gamma,
                                     const float* __restrict__ beta, int lb)
{
    float s = 0.f;
#pragma unroll
    for (int m = 0; m < 32; m++) s += x[m];
    quadred(s);
    float mu = s * 0.0078125f;
    float q = 0.f;
#pragma unroll
    for (int m = 0; m < 32; m++) { x[m] -= mu; q += x[m] * x[m]; }
    quadred(q);
    float rs = rsqrtf(q * 0.0078125f + 1e-5f);
#pragma unroll
    for (int m4 = 0; m4 < 8; m4++) {
        float4 gv = __ldg((const float4*)(gamma + lb) + m4);
        float4 bv = __ldg((const float4*)(beta + lb) + m4);
        x[m4*4+0] = x[m4*4+0] * rs * gv.x + bv.x;
        x[m4*4+1] = x[m4*4+1] * rs * gv.y + bv.y;
        x[m4*4+2] = x[m4*4+2] * rs * gv.z + bv.z;
        x[m4*4+3] = x[m4*4+3] * rs * gv.w + bv.w;
    }
}

// Load one 32k weight chunk (128 logical rows) into registers.
__device__ __forceinline__ void load_chunk(float4 wv[4], const float* __restrict__ Wg,
                                           const float* __restrict__ Ug, int ch, int tid)
{
#pragma unroll
    for (int it = 0; it < 4; it++) {
        int idx = tid + it * 256;
        int l = idx & 127, kk0 = (idx >> 7) * 4;
        int kg = ch * 32 + kk0;
        const float* src = (kg < 128) ? Wg + (size_t)l * 128 + kg
                                      : Ug + (size_t)l * 256 + (kg - 128);
        wv[it] = __ldg((const float4*)src);
    }
}

// Scatter chunk into fragment-packed tf32 layout.
// Logical row l -> phys col p = 8*j + 2*t4 + e  (t4=l>>5, j=(l&31)>>1, e=l&1),
// so logical col of phys fragment (t4,j,e) is t4*32 + 2j + e (contiguous per lane quad).
// Pack: word offset = k8*1024 + v*128 + lane*4 + e2, lane=(p&7)*4+(k&3),
//       idx2 = j*2 + ((k>>2)&1), v=idx2>>2, e2=idx2&3.
__device__ __forceinline__ void stage_sts(uint32_t* bb, const float4 wv[4], int tid)
{
#pragma unroll
    for (int it = 0; it < 4; it++) {
        int idx = tid + it * 256;
        int l = idx & 127, kk0 = (idx >> 7) * 4;
        int t4l = l >> 5, rl = l & 31, j = rl >> 1, e = rl & 1;
        int pn7 = 2 * t4l + e;
        int idx2 = j * 2 + ((kk0 >> 2) & 1);
        uint32_t base = ((uint32_t)(kk0 >> 3) << 10) + ((uint32_t)(idx2 >> 2) << 7)
                      + ((uint32_t)pn7 << 4) + (uint32_t)(idx2 & 3);
        bb[base + 0]  = tf32r(wv[it].x);
        bb[base + 4]  = tf32r(wv[it].y);
        bb[base + 8]  = tf32r(wv[it].z);
        bb[base + 12] = tf32r(wv[it].w);
    }
}

// One gate GEMM: acc[16][4] = A[128x384] @ [Wg|Ug]^T (warp: 16 rows x 128 cols).
__device__ void run_gate(float acc[16][4], const float* __restrict__ Wg,
                         const float* __restrict__ Ug,
                         const uint32_t* sA, uint32_t* sB, int gate,
                         int tid, int lane, int warp)
{
#pragma unroll
    for (int j = 0; j < 16; j++)
#pragma unroll
        for (int q = 0; q < 4; q++) acc[j][q] = 0.f;

    const int g = lane >> 2, t4 = lane & 3;
    const int r0 = warp * 16 + g;
    float4 wv[4];
    load_chunk(wv, Wg, Ug, 0, tid);

    for (int ch = 0; ch < 12; ch++) {
        uint32_t* bb = sB + (((gate * 12 + ch) & 1) ? B_WORDS : 0);
        stage_sts(bb, wv, tid);
        __syncthreads();
        if (ch < 11) load_chunk(wv, Wg, Ug, ch + 1, tid);
#pragma unroll
        for (int k8 = 0; k8 < 4; k8++) {
            int kb = ch * 32 + k8 * 8;
            const uint32_t* ar = sA + r0 * AS + kb;
            uint32_t a0 = ar[t4], a2 = ar[t4 + 4];
            uint32_t a1 = ar[8 * AS + t4], a3 = ar[8 * AS + t4 + 4];
            const uint32_t* bp = bb + k8 * 1024 + lane * 4;
#pragma unroll
            for (int v = 0; v < 8; v++) {
                uint4 bv = *(const uint4*)(bp + v * 128);
                mma8(acc[2 * v],     a0, a1, a2, a3, bv.x, bv.y);
                mma8(acc[2 * v + 1], a0, a1, a2, a3, bv.z, bv.w);
            }
        }
        // single sync per chunk is safe: buffer written next iter was last read
        // two iterations ago, which every thread finished before this sync.
    }
}

__global__ __launch_bounds__(256, 1) void treelstm_mma(
    const float* __restrict__ emb,  const float* __restrict__ h_child,
    const float* __restrict__ c_child, const int* __restrict__ n_type,
    const float* __restrict__ W_iou, const float* __restrict__ U_iou,
    const float* __restrict__ b_iou, const float* __restrict__ W_f,
    const float* __restrict__ U_f,   const float* __restrict__ b_f,
    const float* __restrict__ g_i,  const float* __restrict__ b_i,
    const float* __restrict__ g_o,  const float* __restrict__ b_o,
    const float* __restrict__ g_u,  const float* __restrict__ b_u,
    const float* __restrict__ gn_f, const float* __restrict__ bn_f,
    const float* __restrict__ gn_c, const float* __restrict__ bn_c,
    float* __restrict__ out, int n)
{
    extern __shared__ uint32_t sm[];
    uint32_t* sA = sm;
    uint32_t* sB = sm + 128 * AS;

    const int tid = threadIdx.x;
    const int lane = tid & 31, warp = tid >> 5;
    const int t4 = lane & 3, g = lane >> 2;
    const int lb = t4 * 32;
    const int row0 = blockIdx.x * 128;
    const int rowg[2] = { row0 + warp * 16 + g, row0 + warp * 16 + g + 8 };

    // ---- Phase 0: A = [emb | ht0 | ht1] as tf32, row-major ----
    for (int e = tid; e < 128 * 32; e += 256) {
        int r = e >> 5, k4 = (e & 31) * 4;
        float4 v = __ldg((const float4*)(emb + (size_t)(row0 + r) * 128 + k4));
        uint32_t* d = sA + r * AS + k4;
        d[0] = tf32r(v.x); d[1] = tf32r(v.y); d[2] = tf32r(v.z); d[3] = tf32r(v.w);
    }
    for (int e = tid; e < 128 * 128; e += 256) {
        int r = e >> 7, c = e & 127;
        const float* hp = h_child + ((size_t)(row0 + r) * 4) * 128 + c;
        float h0 = 0.f, h1 = 0.f;
#pragma unroll
        for (int k = 0; k < 4; k++) {
            float v = __ldg(hp + k * 128);
            if (__ldg(n_type + (size_t)(row0 + r) * 4 + k) == 0) h0 += v; else h1 += v;
        }
        sA[r * AS + 128 + c] = tf32r(h0);
        sA[r * AS + 256 + c] = tf32r(h1);
    }
    __syncthreads();

    float acc[16][4];
    float cS[2][32];
    float x[32];

#define GATHER(BIAS)                                                  \
    {                                                                 \
        _Pragma("unroll") for (int j = 0; j < 16; j++) {              \
            x[2 * j]     = acc[j][rr * 2 + 0];                        \
            x[2 * j + 1] = acc[j][rr * 2 + 1];                        \
        }                                                             \
        _Pragma("unroll") for (int m4 = 0; m4 < 8; m4++) {            \
            float4 bv = __ldg((const float4*)((BIAS) + lb) + m4);     \
            x[m4*4+0] += bv.x; x[m4*4+1] += bv.y;                     \
            x[m4*4+2] += bv.z; x[m4*4+3] += bv.w;                     \
        }                                                             \
    }

    // ---- Gate u: cS = tanh(LN(u)) ----
    run_gate(acc, W_iou + 256 * 128, U_iou + 256 * 256, sA, sB, 0, tid, lane, warp);
#pragma unroll
    for (int rr = 0; rr < 2; rr++) {
        GATHER(b_iou + 256);
        ln32(x, g_u, b_u, lb);
#pragma unroll
        for (int m = 0; m < 32; m++) cS[rr][m] = tanhf(x[m]);
    }

    // ---- Gate i: cS *= sigm(LN(i)) ----
    run_gate(acc, W_iou, U_iou, sA, sB, 1, tid, lane, warp);
#pragma unroll
    for (int rr = 0; rr < 2; rr++) {
        GATHER(b_iou);
        ln32(x, g_i, b_i, lb);
#pragma unroll
        for (int m = 0; m < 32; m++) cS[rr][m] *= sigm(x[m]);
    }

    // ---- Gates f0 / f1: cS += sigm(LN(f)) * ct ----
#pragma unroll 1
    for (int ft = 0; ft < 2; ft++) {
        run_gate(acc, W_f, U_f + ft * 128 * 256, sA, sB, 2 + ft, tid, lane, warp);
#pragma unroll
        for (int rr = 0; rr < 2; rr++) {
            GATHER(b_f);
            ln32(x, gn_f, bn_f, lb);
            float ct[32];
#pragma unroll
            for (int m = 0; m < 32; m++) ct[m] = 0.f;
#pragma unroll
            for (int k = 0; k < 4; k++) {
                if (__ldg(n_type + (size_t)rowg[rr] * 4 + k) == ft) {
                    const float4* cp = (const float4*)(c_child
                        + (size_t)rowg[rr] * 512 + k * 128 + lb);
#pragma unroll
                    for (int q = 0; q < 8; q++) {
                        float4 v = __ldg(cp + q);
                        ct[q*4+0] += v.x; ct[q*4+1] += v.y;
                        ct[q*4+2] += v.z; ct[q*4+3] += v.w;
                    }
                }
            }
#pragma unroll
            for (int m = 0; m < 32; m++) cS[rr][m] += sigm(x[m]) * ct[m];
        }
    }

    // ---- write c, then cS := tanh(LN(c)) ----
#pragma unroll
    for (int rr = 0; rr < 2; rr++) {
        float* oc = out + (size_t)n * 128 + (size_t)rowg[rr] * 128 + lb;
#pragma unroll
        for (int q = 0; q < 8; q++)
            *((float4*)oc + q) = make_float4(cS[rr][q*4], cS[rr][q*4+1],
                                             cS[rr][q*4+2], cS[rr][q*4+3]);
#pragma unroll
        for (int m = 0; m < 32; m++) x[m] = cS[rr][m];
        ln32(x, gn_c, bn_c, lb);
#pragma unroll
        for (int m = 0; m < 32; m++) cS[rr][m] = tanhf(x[m]);
    }

    // ---- Gate o: h = sigm(LN(o)) * tanh(LN(c)) ----
    run_gate(acc, W_iou + 128 * 128, U_iou + 128 * 256, sA, sB, 4, tid, lane, warp);
#pragma unroll
    for (int rr = 0; rr < 2; rr++) {
        GATHER(b_iou + 128);
        ln32(x, g_o, b_o, lb);
        float* oh = out + (size_t)rowg[rr] * 128 + lb;
#pragma unroll
        for (int q = 0; q < 8; q++) {
            float4 hv;
            hv.x = sigm(x[q*4+0]) * cS[rr][q*4+0];
            hv.y = sigm(x[q*4+1]) * cS[rr][q*4+1];
            hv.z = sigm(x[q*4+2]) * cS[rr][q*4+2];
            hv.w = sigm(x[q*4+3]) * cS[rr][q*4+3];
            *((float4*)oh + q) = hv;
        }
    }
#undef GATHER
}

extern "C" void kernel_launch(void* const* d_in, const int* in_sizes, int n_in,
                              void* d_out, int out_size)
{
    const float* emb     = (const float*)d_in[0];
    const float* h_child = (const float*)d_in[1];
    const float* c_child = (const float*)d_in[2];
    const int*   n_type  = (const int*)  d_in[3];
    const float* W_iou   = (const float*)d_in[4];
    const float* U_iou   = (const float*)d_in[5];
    const float* b_iou   = (const float*)d_in[6];
    const float* W_f     = (const float*)d_in[7];
    const float* U_f     = (const float*)d_in[8];
    const float* b_f     = (const float*)d_in[9];
    const float* g_i  = (const float*)d_in[10];
    const float* b_i  = (const float*)d_in[11];
    const float* g_o  = (const float*)d_in[12];
    const float* b_o  = (const float*)d_in[13];
    const float* g_u  = (const float*)d_in[14];
    const float* b_u  = (const float*)d_in[15];
    const float* gn_f = (const float*)d_in[16];
    const float* bn_f = (const float*)d_in[17];
    const float* gn_c = (const float*)d_in[18];
    const float* bn_c = (const float*)d_in[19];
    float* out = (float*)d_out;

    int n = in_sizes[0] / 128;

    static int smem_set = 0;
    if (!smem_set) {
        cudaFuncSetAttribute(treelstm_mma,
                             cudaFuncAttributeMaxDynamicSharedMemorySize,
                             SMEM_BYTES);
        smem_set = 1;
    }

    treelstm_mma<<<n / 128, 256, SMEM_BYTES>>>(
        emb, h_child, c_child, n_type, W_iou, U_iou, b_iou, W_f, U_f, b_f,
        g_i, b_i, g_o, b_o, g_u, b_u, gn_f, bn_f, gn_c, bn_c, out, n);
}

// round 12
// speedup vs baseline: 2.0859x; 1.2873x over previous
#include <cuda_runtime.h>
#include <math.h>
#include <stdint.h>

// Fused TreeLSTM cell, tf32 mma.sync (m16n8k8), 512 threads / 16 warps.
// Warp w: rows (w&7)*16..+15, column half (w>>3)*64 of the 128-wide GEMM.
// A=[emb|ht0|ht1] tf32 in smem (XOR-swizzled, stride 384); weights
// fragment-packed + double-buffered; LN via smem partials (2-warp rows).

#define THREADS 512
#define AS 384
#define B_WORDS 4096
#define OFF_B (128 * AS)                  // 49152
#define OFF_P (OFF_B + 2 * B_WORDS)       // 57344 (512 floats of partials)
#define SMEM_WORDS (OFF_P + 512)          // 57856
#define SMEM_BYTES (SMEM_WORDS * 4)       // 231424 <= 232448

__device__ __forceinline__ uint32_t tf32r(float x) {
    uint32_t r; asm("cvt.rna.tf32.f32 %0, %1;" : "=r"(r) : "f"(x)); return r;
}
__device__ __forceinline__ void mma8(float d[4], uint32_t a0, uint32_t a1,
                                     uint32_t a2, uint32_t a3,
                                     uint32_t b0, uint32_t b1)
{
    asm volatile(
        "mma.sync.aligned.m16n8k8.row.col.f32.tf32.tf32.f32 "
        "{%0,%1,%2,%3}, {%4,%5,%6,%7}, {%8,%9}, {%0,%1,%2,%3};"
        : "+f"(d[0]), "+f"(d[1]), "+f"(d[2]), "+f"(d[3])
        : "r"(a0), "r"(a1), "r"(a2), "r"(a3), "r"(b0), "r"(b1));
}
__device__ __forceinline__ float sigm(float x) { return 1.f / (1.f + expf(-x)); }
__device__ __forceinline__ void quadred(float& v)
{
    v += __shfl_xor_sync(0xffffffffu, v, 1);
    v += __shfl_xor_sync(0xffffffffu, v, 2);
}
// A swizzle: word k of row r stored at r*384 + (k ^ ((r&7)*4))
__device__ __forceinline__ int aswz(int r, int k) {
    return r * AS + (k ^ ((r & 7) * 4));
}

// Load one 32k weight chunk (128 logical rows): 2 float4 per thread.
__device__ __forceinline__ void load_chunk(float4 wv[2], const float* __restrict__ Wg,
                                           const float* __restrict__ Ug, int ch, int tid)
{
#pragma unroll
    for (int it = 0; it < 2; it++) {
        int idx = tid + it * 512;
        int l = idx & 127, kk0 = (idx >> 7) * 4;
        int kg = ch * 32 + kk0;
        const float* src = (kg < 128) ? Wg + (size_t)l * 128 + kg
                                      : Ug + (size_t)l * 256 + (kg - 128);
        wv[it] = __ldg((const float4*)src);
    }
}

// Scatter chunk into fragment-packed tf32 layout (same mapping as verified R11).
__device__ __forceinline__ void stage_sts(uint32_t* bb, const float4 wv[2], int tid)
{
#pragma unroll
    for (int it = 0; it < 2; it++) {
        int idx = tid + it * 512;
        int l = idx & 127, kk0 = (idx >> 7) * 4;
        int t4l = l >> 5, rl = l & 31, j = rl >> 1, e = rl & 1;
        int pn7 = 2 * t4l + e;
        int idx2 = j * 2 + ((kk0 >> 2) & 1);
        uint32_t base = ((uint32_t)(kk0 >> 3) << 10) + ((uint32_t)(idx2 >> 2) << 7)
                      + ((uint32_t)pn7 << 4) + (uint32_t)(idx2 & 3);
        bb[base + 0]  = tf32r(wv[it].x);
        bb[base + 4]  = tf32r(wv[it].y);
        bb[base + 8]  = tf32r(wv[it].z);
        bb[base + 12] = tf32r(wv[it].w);
    }
}

// One gate GEMM: warp computes 16 rows x 64 cols (half h of 128).
__device__ void run_gate(float acc[8][4], const float* __restrict__ Wg,
                         const float* __restrict__ Ug,
                         const uint32_t* sA, uint32_t* sB, int gate,
                         int tid, int lane, int warp)
{
#pragma unroll
    for (int j = 0; j < 8; j++)
#pragma unroll
        for (int q = 0; q < 4; q++) acc[j][q] = 0.f;

    const int g = lane >> 2, t4 = lane & 3;
    const int w8 = warp & 7, h = warp >> 3;
    const int r0 = w8 * 16 + g;
    const int g4 = (r0 & 7) * 4;       // same for r0 and r0+8
    float4 wv[2];
    load_chunk(wv, Wg, Ug, 0, tid);

    for (int ch = 0; ch < 12; ch++) {
        uint32_t* bb = sB + (((gate * 12 + ch) & 1) ? B_WORDS : 0);
        stage_sts(bb, wv, tid);
        __syncthreads();
        if (ch < 11) load_chunk(wv, Wg, Ug, ch + 1, tid);
#pragma unroll
        for (int k8 = 0; k8 < 4; k8++) {
            int kb = ch * 32 + k8 * 8;
            const uint32_t* ar  = sA + r0 * AS;
            const uint32_t* ar8 = ar + 8 * AS;
            int o0 = (kb + t4) ^ g4, o4 = (kb + t4 + 4) ^ g4;
            uint32_t a0 = ar[o0],  a2 = ar[o4];
            uint32_t a1 = ar8[o0], a3 = ar8[o4];
            const uint32_t* bp = bb + k8 * 1024 + h * 512 + lane * 4;
#pragma unroll
            for (int vv = 0; vv < 4; vv++) {
                uint4 bv = *(const uint4*)(bp + vv * 128);
                mma8(acc[2 * vv],     a0, a1, a2, a3, bv.x, bv.y);
                mma8(acc[2 * vv + 1], a0, a1, a2, a3, bv.z, bv.w);
            }
        }
        // single sync/chunk safe: buffer written next iter was last read two
        // iterations ago, past this sync for every thread.
    }
}

// LayerNorm over 128-col rows split across warp pair (h / 1-h), 16 cols/lane.
// sP: [128 rows][2 halves] float pairs used in two phases; 2 CTA barriers.
__device__ void ln_pair(float xx[2][16], float* sP, int h, const int rowl[2],
                        const float* __restrict__ gamma,
                        const float* __restrict__ beta, int lb, int t4)
{
    float s[2];
#pragma unroll
    for (int rr = 0; rr < 2; rr++) {
        float v = 0.f;
#pragma unroll
        for (int m = 0; m < 16; m++) v += xx[rr][m];
        quadred(v);
        s[rr] = v;
    }
    if (t4 == 0) {
        sP[rowl[0] * 2 + h] = s[0];
        sP[rowl[1] * 2 + h] = s[1];
    }
    __syncthreads();
    float mu[2];
#pragma unroll
    for (int rr = 0; rr < 2; rr++)
        mu[rr] = (s[rr] + sP[rowl[rr] * 2 + (1 - h)]) * 0.0078125f;
    __syncthreads();
    float q[2];
#pragma unroll
    for (int rr = 0; rr < 2; rr++) {
        float v = 0.f;
#pragma unroll
        for (int m = 0; m < 16; m++) {
            xx[rr][m] -= mu[rr];
            v += xx[rr][m] * xx[rr][m];
        }
        quadred(v);
        q[rr] = v;
    }
    if (t4 == 0) {
        sP[rowl[0] * 2 + h] = q[0];
        sP[rowl[1] * 2 + h] = q[1];
    }
    __syncthreads();
#pragma unroll
    for (int rr = 0; rr < 2; rr++) {
        float rs = rsqrtf((q[rr] + sP[rowl[rr] * 2 + (1 - h)]) * 0.0078125f + 1e-5f);
#pragma unroll
        for (int m4 = 0; m4 < 4; m4++) {
            float4 gv = __ldg((const float4*)(gamma + lb) + m4);
            float4 bv = __ldg((const float4*)(beta + lb) + m4);
            xx[rr][m4*4+0] = xx[rr][m4*4+0] * rs * gv.x + bv.x;
            xx[rr][m4*4+1] = xx[rr][m4*4+1] * rs * gv.y + bv.y;
            xx[rr][m4*4+2] = xx[rr][m4*4+2] * rs * gv.z + bv.z;
            xx[rr][m4*4+3] = xx[rr][m4*4+3] * rs * gv.w + bv.w;
        }
    }
    __syncthreads();   // protect sP reuse by next LN
}

__global__ __launch_bounds__(THREADS, 1) void treelstm_mma(
    const float* __restrict__ emb,  const float* __restrict__ h_child,
    const float* __restrict__ c_child, const int* __restrict__ n_type,
    const float* __restrict__ W_iou, const float* __restrict__ U_iou,
    const float* __restrict__ b_iou, const float* __restrict__ W_f,
    const float* __restrict__ U_f,   const float* __restrict__ b_f,
    const float* __restrict__ g_i,  const float* __restrict__ b_i,
    const float* __restrict__ g_o,  const float* __restrict__ b_o,
    const float* __restrict__ g_u,  const float* __restrict__ b_u,
    const float* __restrict__ gn_f, const float* __restrict__ bn_f,
    const float* __restrict__ gn_c, const float* __restrict__ bn_c,
    float* __restrict__ out, int n)
{
    extern __shared__ uint32_t sm[];
    uint32_t* sA = sm;
    uint32_t* sB = sm + OFF_B;
    float*    sP = (float*)(sm + OFF_P);

    const int tid = threadIdx.x;
    const int lane = tid & 31, warp = tid >> 5;
    const int t4 = lane & 3, g = lane >> 2;
    const int w8 = warp & 7, h = warp >> 3;
    const int lb = t4 * 32 + h * 16;            // 16 logical cols per lane
    const int row0 = blockIdx.x * 128;
    const int rowl[2] = { w8 * 16 + g, w8 * 16 + g + 8 };
    const int rowg[2] = { row0 + rowl[0], row0 + rowl[1] };

    // ---- Phase 0: A = [emb | ht0 | ht1] as tf32 (swizzled) ----
    for (int e = tid; e < 128 * 32; e += THREADS) {
        int r = e >> 5, k4 = (e & 31) * 4;
        float4 v = __ldg((const float4*)(emb + (size_t)(row0 + r) * 128 + k4));
        sA[aswz(r, k4 + 0)] = tf32r(v.x);
        sA[aswz(r, k4 + 1)] = tf32r(v.y);
        sA[aswz(r, k4 + 2)] = tf32r(v.z);
        sA[aswz(r, k4 + 3)] = tf32r(v.w);
    }
    for (int e = tid; e < 128 * 128; e += THREADS) {
        int r = e >> 7, c = e & 127;
        const float* hp = h_child + ((size_t)(row0 + r) * 4) * 128 + c;
        float h0 = 0.f, h1 = 0.f;
#pragma unroll
        for (int k = 0; k < 4; k++) {
            float v = __ldg(hp + k * 128);
            if (__ldg(n_type + (size_t)(row0 + r) * 4 + k) == 0) h0 += v; else h1 += v;
        }
        sA[aswz(r, 128 + c)] = tf32r(h0);
        sA[aswz(r, 256 + c)] = tf32r(h1);
    }
    __syncthreads();

    float acc[8][4];
    float cS[2][16];
    float xx[2][16];

#define GATHER16(BIAS)                                                   \
    _Pragma("unroll") for (int rr = 0; rr < 2; rr++) {                   \
        _Pragma("unroll") for (int jl = 0; jl < 8; jl++) {               \
            xx[rr][2 * jl]     = acc[jl][rr * 2 + 0];                    \
            xx[rr][2 * jl + 1] = acc[jl][rr * 2 + 1];                    \
        }                                                                \
        _Pragma("unroll") for (int m4 = 0; m4 < 4; m4++) {               \
            float4 bv = __ldg((const float4*)((BIAS) + lb) + m4);        \
            xx[rr][m4*4+0] += bv.x; xx[rr][m4*4+1] += bv.y;              \
            xx[rr][m4*4+2] += bv.z; xx[rr][m4*4+3] += bv.w;              \
        }                                                                \
    }

    // ---- Gate u ----
    run_gate(acc, W_iou + 256 * 128, U_iou + 256 * 256, sA, sB, 0, tid, lane, warp);
    GATHER16(b_iou + 256);
    ln_pair(xx, sP, h, rowl, g_u, b_u, lb, t4);
#pragma unroll
    for (int rr = 0; rr < 2; rr++)
#pragma unroll
        for (int m = 0; m < 16; m++) cS[rr][m] = tanhf(xx[rr][m]);

    // ---- Gate i ----
    run_gate(acc, W_iou, U_iou, sA, sB, 1, tid, lane, warp);
    GATHER16(b_iou);
    ln_pair(xx, sP, h, rowl, g_i, b_i, lb, t4);
#pragma unroll
    for (int rr = 0; rr < 2; rr++)
#pragma unroll
        for (int m = 0; m < 16; m++) cS[rr][m] *= sigm(xx[rr][m]);

    // ---- Gates f0 / f1 ----
#pragma unroll 1
    for (int ft = 0; ft < 2; ft++) {
        run_gate(acc, W_f, U_f + ft * 128 * 256, sA, sB, 2 + ft, tid, lane, warp);
        GATHER16(b_f);
        ln_pair(xx, sP, h, rowl, gn_f, bn_f, lb, t4);
#pragma unroll
        for (int rr = 0; rr < 2; rr++) {
            float ct[16];
#pragma unroll
            for (int m = 0; m < 16; m++) ct[m] = 0.f;
#pragma unroll
            for (int k = 0; k < 4; k++) {
                if (__ldg(n_type + (size_t)rowg[rr] * 4 + k) == ft) {
                    const float4* cp = (const float4*)(c_child
                        + (size_t)rowg[rr] * 512 + k * 128 + lb);
#pragma unroll
                    for (int q = 0; q < 4; q++) {
                        float4 v = __ldg(cp + q);
                        ct[q*4+0] += v.x; ct[q*4+1] += v.y;
                        ct[q*4+2] += v.z; ct[q*4+3] += v.w;
                    }
                }
            }
#pragma unroll
            for (int m = 0; m < 16; m++) cS[rr][m] += sigm(xx[rr][m]) * ct[m];
        }
    }

    // ---- write c; cS := tanh(LN(c)) ----
#pragma unroll
    for (int rr = 0; rr < 2; rr++) {
        float* oc = out + (size_t)n * 128 + (size_t)rowg[rr] * 128 + lb;
#pragma unroll
        for (int q = 0; q < 4; q++)
            *((float4*)oc + q) = make_float4(cS[rr][q*4], cS[rr][q*4+1],
                                             cS[rr][q*4+2], cS[rr][q*4+3]);
#pragma unroll
        for (int m = 0; m < 16; m++) xx[rr][m] = cS[rr][m];
    }
    ln_pair(xx, sP, h, rowl, gn_c, bn_c, lb, t4);
#pragma unroll
    for (int rr = 0; rr < 2; rr++)
#pragma unroll
        for (int m = 0; m < 16; m++) cS[rr][m] = tanhf(xx[rr][m]);

    // ---- Gate o: h = sigm(LN(o)) * tanh(LN(c)) ----
    run_gate(acc, W_iou + 128 * 128, U_iou + 128 * 256, sA, sB, 4, tid, lane, warp);
    GATHER16(b_iou + 128);
    ln_pair(xx, sP, h, rowl, g_o, b_o, lb, t4);
#pragma unroll
    for (int rr = 0; rr < 2; rr++) {
        float* oh = out + (size_t)rowg[rr] * 128 + lb;
#pragma unroll
        for (int q = 0; q < 4; q++) {
            float4 hv;
            hv.x = sigm(xx[rr][q*4+0]) * cS[rr][q*4+0];
            hv.y = sigm(xx[rr][q*4+1]) * cS[rr][q*4+1];
            hv.z = sigm(xx[rr][q*4+2]) * cS[rr][q*4+2];
            hv.w = sigm(xx[rr][q*4+3]) * cS[rr][q*4+3];
            *((float4*)oh + q) = hv;
        }
    }
#undef GATHER16
}

extern "C" void kernel_launch(void* const* d_in, const int* in_sizes, int n_in,
                              void* d_out, int out_size)
{
    const float* emb     = (const float*)d_in[0];
    const float* h_child = (const float*)d_in[1];
    const float* c_child = (const float*)d_in[2];
    const int*   n_type  = (const int*)  d_in[3];
    const float* W_iou   = (const float*)d_in[4];
    const float* U_iou   = (const float*)d_in[5];
    const float* b_iou   = (const float*)d_in[6];
    const float* W_f     = (const float*)d_in[7];
    const float* U_f     = (const float*)d_in[8];
    const float* b_f     = (const float*)d_in[9];
    const float* g_i  = (const float*)d_in[10];
    const float* b_i  = (const float*)d_in[11];
    const float* g_o  = (const float*)d_in[12];
    const float* b_o  = (const float*)d_in[13];
    const float* g_u  = (const float*)d_in[14];
    const float* b_u  = (const float*)d_in[15];
    const float* gn_f = (const float*)d_in[16];
    const float* bn_f = (const float*)d_in[17];
    const float* gn_c = (const float*)d_in[18];
    const float* bn_c = (const float*)d_in[19];
    float* out = (float*)d_out;

    int n = in_sizes[0] / 128;

    static int smem_set = 0;
    if (!smem_set) {
        cudaFuncSetAttribute(treelstm_mma,
                             cudaFuncAttributeMaxDynamicSharedMemorySize,
                             SMEM_BYTES);
        smem_set = 1;
    }

    treelstm_mma<<<n / 128, THREADS, SMEM_BYTES>>>(
        emb, h_child, c_child, n_type, W_iou, U_iou, b_iou, W_f, U_f, b_f,
        g_i, b_i, g_o, b_o, g_u, b_u, gn_f, bn_f, gn_c, bn_c, out, n);
}

// round 13
// speedup vs baseline: 2.9150x; 1.3975x over previous
#include <cuda_runtime.h>
#include <math.h>
#include <stdint.h>

// Fused TreeLSTM cell, tf32 mma.sync (m16n8k8), 512 threads / 16 warps.
// Warp = (rg, cq): rows rg*32..+31 (2 m16 tiles), cols cq*32..+31 (4 n8 tiles).
// A=[emb|ht0|ht1] tf32 in smem (XOR swizzle, stride 384); B chunks staged in
// natural [c][k32] layout with XOR swizzle; f0/f1 share the W_f*emb partial.

#define THREADS 512
#define AS 384
#define B_WORDS 4096                       // 128 c x 32 k
#define OFF_B (128 * AS)                   // 49152
#define OFF_P (OFF_B + 2 * B_WORDS)        // 57344 (128 rows x 4 partials)
#define SMEM_WORDS (OFF_P + 512)
#define SMEM_BYTES (SMEM_WORDS * 4)        // 231424 <= 232448

__device__ __forceinline__ uint32_t tf32r(float x) {
    uint32_t r; asm("cvt.rna.tf32.f32 %0, %1;" : "=r"(r) : "f"(x)); return r;
}
__device__ __forceinline__ void mma8(float d[4], uint32_t a0, uint32_t a1,
                                     uint32_t a2, uint32_t a3,
                                     uint32_t b0, uint32_t b1)
{
    asm volatile(
        "mma.sync.aligned.m16n8k8.row.col.f32.tf32.tf32.f32 "
        "{%0,%1,%2,%3}, {%4,%5,%6,%7}, {%8,%9}, {%0,%1,%2,%3};"
        : "+f"(d[0]), "+f"(d[1]), "+f"(d[2]), "+f"(d[3])
        : "r"(a0), "r"(a1), "r"(a2), "r"(a3), "r"(b0), "r"(b1));
}
__device__ __forceinline__ float sigm(float x) { return 1.f / (1.f + expf(-x)); }
__device__ __forceinline__ void quadred(float& v)
{
    v += __shfl_xor_sync(0xffffffffu, v, 1);
    v += __shfl_xor_sync(0xffffffffu, v, 2);
}
// A: word k of row r at r*384 + (k ^ ((r&7)*4))
__device__ __forceinline__ int aswz(int r, int k) {
    return r * AS + (k ^ ((r & 7) * 4));
}

// Weight chunk load: thread owns row c_ (0..127), k-slot ks (0,8,16,24).
__device__ __forceinline__ void load_chunk(float4 wv[2], const float* __restrict__ Wg,
                                           const float* __restrict__ Ug,
                                           int ch, int c_, int ks)
{
    int kg = ch * 32 + ks;
    const float* src = (kg < 128) ? Wg + (size_t)c_ * 128 + kg
                                  : Ug + (size_t)c_ * 256 + (kg - 128);
    wv[0] = __ldg((const float4*)src);
    wv[1] = __ldg((const float4*)(src + 4));
}
// Stage into natural layout [c][k32] with k ^ ((c&7)*4) swizzle.
__device__ __forceinline__ void stage(uint32_t* bb, const float4 wv[2], int c_, int ks)
{
    int s = (c_ & 7) * 4;
    uint32_t* p = bb + c_ * 32;
    uint4 t0 = { tf32r(wv[0].x), tf32r(wv[0].y), tf32r(wv[0].z), tf32r(wv[0].w) };
    uint4 t1 = { tf32r(wv[1].x), tf32r(wv[1].y), tf32r(wv[1].z), tf32r(wv[1].w) };
    *(uint4*)(p + (ks ^ s))       = t0;
    *(uint4*)(p + ((ks + 4) ^ s)) = t1;
}

// GEMM chunks [ch0, ch1): acc += A[rows] @ [Wg|Ug]^T[cols]. No acc zeroing.
__device__ void run_gate(float acc[2][4][4], const float* __restrict__ Wg,
                         const float* __restrict__ Ug,
                         const uint32_t* sA, uint32_t* sB, int& gc,
                         int ch0, int ch1, int c_, int ks,
                         int rg, int cq, int g, int t4)
{
    float4 wv[2];
    load_chunk(wv, Wg, Ug, ch0, c_, ks);
    const uint32_t* ar0 = sA + (rg * 32 + g) * AS;
    const int gs4 = g * 4;

    for (int ch = ch0; ch < ch1; ch++) {
        uint32_t* bb = sB + ((gc & 1) ? B_WORDS : 0);
        gc++;
        stage(bb, wv, c_, ks);
        __syncthreads();
        if (ch + 1 < ch1) load_chunk(wv, Wg, Ug, ch + 1, c_, ks);
        const uint32_t* bq = bb + cq * 1024;
#pragma unroll
        for (int k8 = 0; k8 < 4; k8++) {
            int ob = (k8 * 8 + t4) ^ gs4;      // B word offset (local k)
            int ao = ob + ch * 32;             // A word offset (global k)
            uint32_t a00 = ar0[ao],            a10 = ar0[8 * AS + ao];
            uint32_t a20 = ar0[ao ^ 4],        a30 = ar0[8 * AS + (ao ^ 4)];
            uint32_t a01 = ar0[16 * AS + ao],  a11 = ar0[24 * AS + ao];
            uint32_t a21 = ar0[16 * AS + (ao ^ 4)], a31 = ar0[24 * AS + (ao ^ 4)];
#pragma unroll
            for (int n8 = 0; n8 < 4; n8++) {
                const uint32_t* bp = bq + n8 * 256 + g * 32;
                uint32_t b0 = bp[ob], b1 = bp[ob ^ 4];
                mma8(acc[0][n8], a00, a10, a20, a30, b0, b1);
                mma8(acc[1][n8], a01, a11, a21, a31, b0, b1);
            }
        }
        // single sync/chunk: buffer staged next iter was last read two
        // iterations ago, past this iteration's sync for every thread.
    }
}

// LayerNorm over 128-col rows split across 4 col-quarter warps; lane holds
// 4 rows x 8 cols. 3 CTA barriers; sP[row][4] partials.
__device__ void ln4(float xx[4][8], float* sP, const int rl[4], int cq, int t4,
                    const float* __restrict__ gamma,
                    const float* __restrict__ beta, int cb)
{
    float s[4];
#pragma unroll
    for (int i = 0; i < 4; i++) {
        float v = 0.f;
#pragma unroll
        for (int j = 0; j < 8; j++) v += xx[i][j];
        quadred(v);
        s[i] = v;
    }
    if (t4 == 0)
#pragma unroll
        for (int i = 0; i < 4; i++) sP[rl[i] * 4 + cq] = s[i];
    __syncthreads();
    float mu[4];
#pragma unroll
    for (int i = 0; i < 4; i++)
        mu[i] = (sP[rl[i] * 4] + sP[rl[i] * 4 + 1]
               + sP[rl[i] * 4 + 2] + sP[rl[i] * 4 + 3]) * 0.0078125f;
    __syncthreads();
    float q[4];
#pragma unroll
    for (int i = 0; i < 4; i++) {
        float v = 0.f;
#pragma unroll
        for (int j = 0; j < 8; j++) {
            xx[i][j] -= mu[i];
            v += xx[i][j] * xx[i][j];
        }
        quadred(v);
        q[i] = v;
    }
    if (t4 == 0)
#pragma unroll
        for (int i = 0; i < 4; i++) sP[rl[i] * 4 + cq] = q[i];
    __syncthreads();
#pragma unroll
    for (int i = 0; i < 4; i++) {
        float rs = rsqrtf((sP[rl[i] * 4] + sP[rl[i] * 4 + 1]
                         + sP[rl[i] * 4 + 2] + sP[rl[i] * 4 + 3])
                          * 0.0078125f + 1e-5f);
#pragma unroll
        for (int n8 = 0; n8 < 4; n8++) {
            float2 gv = __ldg((const float2*)(gamma + cb + n8 * 8));
            float2 bv = __ldg((const float2*)(beta  + cb + n8 * 8));
            xx[i][2 * n8]     = xx[i][2 * n8]     * rs * gv.x + bv.x;
            xx[i][2 * n8 + 1] = xx[i][2 * n8 + 1] * rs * gv.y + bv.y;
        }
    }
    // no trailing sync: sP next written a full gate (many syncs) later
}

__global__ __launch_bounds__(THREADS, 1) void treelstm_mma(
    const float* __restrict__ emb,  const float* __restrict__ h_child,
    const float* __restrict__ c_child, const int* __restrict__ n_type,
    const float* __restrict__ W_iou, const float* __restrict__ U_iou,
    const float* __restrict__ b_iou, const float* __restrict__ W_f,
    const float* __restrict__ U_f,   const float* __restrict__ b_f,
    const float* __restrict__ g_i,  const float* __restrict__ b_i,
    const float* __restrict__ g_o,  const float* __restrict__ b_o,
    const float* __restrict__ g_u,  const float* __restrict__ b_u,
    const float* __restrict__ gn_f, const float* __restrict__ bn_f,
    const float* __restrict__ gn_c, const float* __restrict__ bn_c,
    float* __restrict__ out, int n)
{
    extern __shared__ uint32_t sm[];
    uint32_t* sA = sm;
    uint32_t* sB = sm + OFF_B;
    float*    sP = (float*)(sm + OFF_P);

    const int tid = threadIdx.x;
    const int lane = tid & 31, warp = tid >> 5;
    const int t4 = lane & 3, g = lane >> 2;
    const int rg = warp & 3, cq = warp >> 2;
    const int cb = cq * 32 + t4 * 2;              // lane's col base (pairs stride 8)
    const int c_ = tid >> 2, ks = (tid & 3) * 8;  // staging coords
    const int row0 = blockIdx.x * 128;
    const int rl[4] = { rg * 32 + g, rg * 32 + g + 8,
                        rg * 32 + g + 16, rg * 32 + g + 24 };

    // ---- Phase 0: A = [emb | ht0 | ht1] as tf32 (swizzled) ----
    for (int e = tid; e < 128 * 32; e += THREADS) {
        int r = e >> 5, k4 = (e & 31) * 4;
        float4 v = __ldg((const float4*)(emb + (size_t)(row0 + r) * 128 + k4));
        sA[aswz(r, k4 + 0)] = tf32r(v.x);
        sA[aswz(r, k4 + 1)] = tf32r(v.y);
        sA[aswz(r, k4 + 2)] = tf32r(v.z);
        sA[aswz(r, k4 + 3)] = tf32r(v.w);
    }
    for (int e = tid; e < 128 * 128; e += THREADS) {
        int r = e >> 7, c = e & 127;
        const float* hp = h_child + ((size_t)(row0 + r) * 4) * 128 + c;
        float h0 = 0.f, h1 = 0.f;
#pragma unroll
        for (int k = 0; k < 4; k++) {
            float v = __ldg(hp + k * 128);
            if (__ldg(n_type + (size_t)(row0 + r) * 4 + k) == 0) h0 += v; else h1 += v;
        }
        sA[aswz(r, 128 + c)] = tf32r(h0);
        sA[aswz(r, 256 + c)] = tf32r(h1);
    }
    __syncthreads();

    float acc[2][4][4], X[2][4][4], cS[4][8], xx[4][8];
    int gc = 0;

#define ZACC()                                                \
    _Pragma("unroll") for (int m = 0; m < 2; m++)             \
    _Pragma("unroll") for (int n8 = 0; n8 < 4; n8++)          \
    _Pragma("unroll") for (int q = 0; q < 4; q++) acc[m][n8][q] = 0.f;

#define GATHER(BIAS)                                                   \
    _Pragma("unroll") for (int n8 = 0; n8 < 4; n8++) {                 \
        float2 bv = __ldg((const float2*)((BIAS) + cb + n8 * 8));      \
        xx[0][2*n8]   = acc[0][n8][0] + bv.x;                          \
        xx[0][2*n8+1] = acc[0][n8][1] + bv.y;                          \
        xx[1][2*n8]   = acc[0][n8][2] + bv.x;                          \
        xx[1][2*n8+1] = acc[0][n8][3] + bv.y;                          \
        xx[2][2*n8]   = acc[1][n8][0] + bv.x;                          \
        xx[2][2*n8+1] = acc[1][n8][1] + bv.y;                          \
        xx[3][2*n8]   = acc[1][n8][2] + bv.x;                          \
        xx[3][2*n8+1] = acc[1][n8][3] + bv.y;                          \
    }

    // ---- Gate u: cS = tanh(LN(u)) ----
    ZACC();
    run_gate(acc, W_iou + 256 * 128, U_iou + 256 * 256, sA, sB, gc, 0, 12,
             c_, ks, rg, cq, g, t4);
    GATHER(b_iou + 256);
    ln4(xx, sP, rl, cq, t4, g_u, b_u, cb);
#pragma unroll
    for (int i = 0; i < 4; i++)
#pragma unroll
        for (int j = 0; j < 8; j++) cS[i][j] = tanhf(xx[i][j]);

    // ---- Gate i: cS *= sigm(LN(i)) ----
    ZACC();
    run_gate(acc, W_iou, U_iou, sA, sB, gc, 0, 12, c_, ks, rg, cq, g, t4);
    GATHER(b_iou);
    ln4(xx, sP, rl, cq, t4, g_i, b_i, cb);
#pragma unroll
    for (int i = 0; i < 4; i++)
#pragma unroll
        for (int j = 0; j < 8; j++) cS[i][j] *= sigm(xx[i][j]);

    // ---- Gate f0: X = W_f*emb (shared); f0 = X + U_f0*hio ----
    ZACC();
    run_gate(acc, W_f, U_f, sA, sB, gc, 0, 4, c_, ks, rg, cq, g, t4);
#pragma unroll
    for (int m = 0; m < 2; m++)
#pragma unroll
        for (int n8 = 0; n8 < 4; n8++)
#pragma unroll
            for (int q = 0; q < 4; q++) X[m][n8][q] = acc[m][n8][q];
    run_gate(acc, W_f, U_f, sA, sB, gc, 4, 12, c_, ks, rg, cq, g, t4);
#pragma unroll 1
    for (int ft = 0; ft < 2; ft++) {
        GATHER(b_f);
        ln4(xx, sP, rl, cq, t4, gn_f, bn_f, cb);
#pragma unroll
        for (int i = 0; i < 4; i++) {
            size_t grow = (size_t)(row0 + rl[i]);
            int4 nt = __ldg((const int4*)(n_type + grow * 4));
            int ntk[4] = { nt.x, nt.y, nt.z, nt.w };
            float ct[8] = { 0.f, 0.f, 0.f, 0.f, 0.f, 0.f, 0.f, 0.f };
#pragma unroll
            for (int k = 0; k < 4; k++) {
                if (ntk[k] == ft) {
                    const float* cp = c_child + grow * 512 + k * 128 + cb;
#pragma unroll
                    for (int n8 = 0; n8 < 4; n8++) {
                        float2 v = __ldg((const float2*)(cp + n8 * 8));
                        ct[2 * n8] += v.x; ct[2 * n8 + 1] += v.y;
                    }
                }
            }
#pragma unroll
            for (int j = 0; j < 8; j++) cS[i][j] += sigm(xx[i][j]) * ct[j];
        }
        if (ft == 0) {
            // ---- Gate f1: acc = X + U_f1*hio ----
#pragma unroll
            for (int m = 0; m < 2; m++)
#pragma unroll
                for (int n8 = 0; n8 < 4; n8++)
#pragma unroll
                    for (int q = 0; q < 4; q++) acc[m][n8][q] = X[m][n8][q];
            run_gate(acc, W_f, U_f + 128 * 256, sA, sB, gc, 4, 12,
                     c_, ks, rg, cq, g, t4);
        }
    }

    // ---- write c; cS := tanh(LN(c)) ----
#pragma unroll
    for (int i = 0; i < 4; i++) {
        float* oc = out + (size_t)n * 128 + (size_t)(row0 + rl[i]) * 128 + cb;
#pragma unroll
        for (int n8 = 0; n8 < 4; n8++) {
            *(float2*)(oc + n8 * 8) = make_float2(cS[i][2*n8], cS[i][2*n8+1]);
            xx[i][2*n8] = cS[i][2*n8]; xx[i][2*n8+1] = cS[i][2*n8+1];
        }
    }
    ln4(xx, sP, rl, cq, t4, gn_c, bn_c, cb);
#pragma unroll
    for (int i = 0; i < 4; i++)
#pragma unroll
        for (int j = 0; j < 8; j++) cS[i][j] = tanhf(xx[i][j]);

    // ---- Gate o: h = sigm(LN(o)) * tanh(LN(c)) ----
    ZACC();
    run_gate(acc, W_iou + 128 * 128, U_iou + 128 * 256, sA, sB, gc, 0, 12,
             c_, ks, rg, cq, g, t4);
    GATHER(b_iou + 128);
    ln4(xx, sP, rl, cq, t4, g_o, b_o, cb);
#pragma unroll
    for (int i = 0; i < 4; i++) {
        float* oh = out + (size_t)(row0 + rl[i]) * 128 + cb;
#pragma unroll
        for (int n8 = 0; n8 < 4; n8++)
            *(float2*)(oh + n8 * 8) = make_float2(sigm(xx[i][2*n8])   * cS[i][2*n8],
                                                  sigm(xx[i][2*n8+1]) * cS[i][2*n8+1]);
    }
#undef GATHER
#undef ZACC
}

extern "C" void kernel_launch(void* const* d_in, const int* in_sizes, int n_in,
                              void* d_out, int out_size)
{
    const float* emb     = (const float*)d_in[0];
    const float* h_child = (const float*)d_in[1];
    const float* c_child = (const float*)d_in[2];
    const int*   n_type  = (const int*)  d_in[3];
    const float* W_iou   = (const float*)d_in[4];
    const float* U_iou   = (const float*)d_in[5];
    const float* b_iou   = (const float*)d_in[6];
    const float* W_f     = (const float*)d_in[7];
    const float* U_f     = (const float*)d_in[8];
    const float* b_f     = (const float*)d_in[9];
    const float* g_i  = (const float*)d_in[10];
    const float* b_i  = (const float*)d_in[11];
    const float* g_o  = (const float*)d_in[12];
    const float* b_o  = (const float*)d_in[13];
    const float* g_u  = (const float*)d_in[14];
    const float* b_u  = (const float*)d_in[15];
    const float* gn_f = (const float*)d_in[16];
    const float* bn_f = (const float*)d_in[17];
    const float* gn_c = (const float*)d_in[18];
    const float* bn_c = (const float*)d_in[19];
    float* out = (float*)d_out;

    int n = in_sizes[0] / 128;

    static int smem_set = 0;
    if (!smem_set) {
        cudaFuncSetAttribute(treelstm_mma,
                             cudaFuncAttributeMaxDynamicSharedMemorySize,
                             SMEM_BYTES);
        smem_set = 1;
    }

    treelstm_mma<<<n / 128, THREADS, SMEM_BYTES>>>(
        emb, h_child, c_child, n_type, W_iou, U_iou, b_iou, W_f, U_f, b_f,
        g_i, b_i, g_o, b_o, g_u, b_u, gn_f, bn_f, gn_c, bn_c, out, n);
}

// round 14
// speedup vs baseline: 2.9647x; 1.0170x over previous
#include <cuda_runtime.h>
#include <math.h>
#include <stdint.h>

// Fused TreeLSTM cell, tf32 mma.sync (m16n8k8), 512 threads / 16 warps.
// Warp (rg, cq): rows rg*32..+31, cols cq*32..+31.
// A and B both stored in smem in MMA-fragment-packed order (uint4 granules,
// XOR-swizzled) so the consumer inner loop is 4 LDS.128 + 8 MMA per k8.

#define THREADS 512
#define B_WORDS 4096                       // one 32k x 128c chunk
#define OFF_B (128 * 384)                  // packed A = 49152 words
#define OFF_P (OFF_B + 2 * B_WORDS)        // 57344 (128 rows x 4 partials)
#define SMEM_WORDS (OFF_P + 512)
#define SMEM_BYTES (SMEM_WORDS * 4)        // 231424 <= 232448

__device__ __forceinline__ uint32_t tf32r(float x) {
    uint32_t r; asm("cvt.rna.tf32.f32 %0, %1;" : "=r"(r) : "f"(x)); return r;
}
__device__ __forceinline__ void mma8(float d[4], uint32_t a0, uint32_t a1,
                                     uint32_t a2, uint32_t a3,
                                     uint32_t b0, uint32_t b1)
{
    asm volatile(
        "mma.sync.aligned.m16n8k8.row.col.f32.tf32.tf32.f32 "
        "{%0,%1,%2,%3}, {%4,%5,%6,%7}, {%8,%9}, {%0,%1,%2,%3};"
        : "+f"(d[0]), "+f"(d[1]), "+f"(d[2]), "+f"(d[3])
        : "r"(a0), "r"(a1), "r"(a2), "r"(a3), "r"(b0), "r"(b1));
}
__device__ __forceinline__ float sigm(float x) { return 1.f / (1.f + expf(-x)); }
__device__ __forceinline__ void quadred(float& v)
{
    v += __shfl_xor_sync(0xffffffffu, v, 1);
    v += __shfl_xor_sync(0xffffffffu, v, 2);
}

// ---- packed-A store: element (r, k) -> fragment position ----
// layout u4 index: k8*256 + rg*64 + lane*2 + m, swizzled by ((g ^ 2*(k8&3))&7).
// lane = g*4 + t4 owns rows {rg*32 + m*16 + hi*8 + g}, k = k8*8 + kof*4 + t4.
__device__ __forceinline__ void storeA(uint32_t* sA, int r, int k, float v)
{
    int rg = r >> 5, m = (r >> 4) & 1, hi = (r >> 3) & 1, g = r & 7;
    int k8 = k >> 3, kof = (k >> 2) & 1, t4 = k & 3;
    int l = g * 4 + t4;
    uint32_t u4 = (uint32_t)(k8 * 256 + rg * 64 + l * 2 + m)
                ^ (uint32_t)((g ^ (2 * (k8 & 3))) & 7);
    sA[u4 * 4 + kof * 2 + hi] = tf32r(v);
}

// Weight chunk load: thread owns row c_ (0..127), k8-slot k8s (0..3).
__device__ __forceinline__ void load_chunk(float4 wv[2], const float* __restrict__ Wg,
                                           const float* __restrict__ Ug,
                                           int ch, int c_, int k8s)
{
    int kg = ch * 32 + k8s * 8;
    const float* src = (kg < 128) ? Wg + (size_t)c_ * 128 + kg
                                  : Ug + (size_t)c_ * 256 + (kg - 128);
    wv[0] = __ldg((const float4*)src);
    wv[1] = __ldg((const float4*)(src + 4));
}

// ---- packed-B stage: element (c_, chunk-local k) -> fragment position ----
// u4 index: cq*256 + k8s*64 + l*2 + (n8>>1), swizzled by ((g ^ 2*k8s)&7).
// pairs (k, k+4) are adjacent words -> STS.64.
__device__ __forceinline__ void stageB(uint32_t* bb, const float4 wv[2],
                                       int c_, int k8s)
{
    int cq = c_ >> 5, n8h = (c_ >> 4) & 1, n8l = (c_ >> 3) & 1, g = c_ & 7;
    uint32_t fw = (uint32_t)((g ^ (2 * k8s)) & 7);
    uint32_t u4b = (uint32_t)(cq * 256 + k8s * 64 + n8h);
    const float* w0 = (const float*)&wv[0];
    const float* w1 = (const float*)&wv[1];
#pragma unroll
    for (int t4e = 0; t4e < 4; t4e++) {
        uint32_t u4s = (u4b + (uint32_t)(g * 4 + t4e) * 2) ^ fw;
        uint2 pr = { tf32r(w0[t4e]), tf32r(w1[t4e]) };
        *(uint2*)((char*)bb + u4s * 16 + n8l * 8) = pr;
    }
}

// GEMM chunks [ch0, ch1): acc += A[rows] @ [Wg|Ug]^T[cols].
__device__ void run_gate(float acc[2][4][4], const float* __restrict__ Wg,
                         const float* __restrict__ Ug,
                         const char* sAp, char* sBp, int& gc,
                         int ch0, int ch1, int c_, int k8s,
                         int rg, int cq, int lane)
{
    // hoisted fragment offsets (bytes); f identical for A and B
    uint32_t aoff0[4], aoff1[4], boff0[4], boff1[4];
#pragma unroll
    for (int k8l = 0; k8l < 4; k8l++) {
        uint32_t f = (uint32_t)(((lane >> 2) ^ (2 * k8l)) & 7);
        aoff0[k8l] = (uint32_t)(k8l * 256 + rg * 64 + ((lane * 2 + 0) ^ f)) * 16;
        aoff1[k8l] = (uint32_t)(k8l * 256 + rg * 64 + ((lane * 2 + 1) ^ f)) * 16;
        boff0[k8l] = (uint32_t)(k8l * 64 + ((lane * 2 + 0) ^ f)) * 16;
        boff1[k8l] = (uint32_t)(k8l * 64 + ((lane * 2 + 1) ^ f)) * 16;
    }

    float4 wv[2];
    load_chunk(wv, Wg, Ug, ch0, c_, k8s);

    for (int ch = ch0; ch < ch1; ch++) {
        char* bb = sBp + ((gc & 1) ? 16384 : 0);
        gc++;
        stageB((uint32_t*)bb, wv, c_, k8s);
        __syncthreads();
        if (ch + 1 < ch1) load_chunk(wv, Wg, Ug, ch + 1, c_, k8s);
        const char* pA = sAp + ch * 16384;
        const char* pB = bb + cq * 4096;
#pragma unroll
        for (int k8l = 0; k8l < 4; k8l++) {
            uint4 aa0 = *(const uint4*)(pA + aoff0[k8l]);
            uint4 aa1 = *(const uint4*)(pA + aoff1[k8l]);
            uint4 b0  = *(const uint4*)(pB + boff0[k8l]);
            uint4 b1  = *(const uint4*)(pB + boff1[k8l]);
            mma8(acc[0][0], aa0.x, aa0.y, aa0.z, aa0.w, b0.x, b0.y);
            mma8(acc[0][1], aa0.x, aa0.y, aa0.z, aa0.w, b0.z, b0.w);
            mma8(acc[0][2], aa0.x, aa0.y, aa0.z, aa0.w, b1.x, b1.y);
            mma8(acc[0][3], aa0.x, aa0.y, aa0.z, aa0.w, b1.z, b1.w);
            mma8(acc[1][0], aa1.x, aa1.y, aa1.z, aa1.w, b0.x, b0.y);
            mma8(acc[1][1], aa1.x, aa1.y, aa1.z, aa1.w, b0.z, b0.w);
            mma8(acc[1][2], aa1.x, aa1.y, aa1.z, aa1.w, b1.x, b1.y);
            mma8(acc[1][3], aa1.x, aa1.y, aa1.z, aa1.w, b1.z, b1.w);
        }
        // single sync/chunk: buffer staged next iter was last read two
        // iterations ago, past this iteration's sync for every thread.
    }
}

// LayerNorm over 128-col rows split across 4 col-quarter warps (unchanged R13).
__device__ void ln4(float xx[4][8], float* sP, const int rl[4], int cq, int t4,
                    const float* __restrict__ gamma,
                    const float* __restrict__ beta, int cb)
{
    float s[4];
#pragma unroll
    for (int i = 0; i < 4; i++) {
        float v = 0.f;
#pragma unroll
        for (int j = 0; j < 8; j++) v += xx[i][j];
        quadred(v);
        s[i] = v;
    }
    if (t4 == 0)
#pragma unroll
        for (int i = 0; i < 4; i++) sP[rl[i] * 4 + cq] = s[i];
    __syncthreads();
    float mu[4];
#pragma unroll
    for (int i = 0; i < 4; i++)
        mu[i] = (sP[rl[i] * 4] + sP[rl[i] * 4 + 1]
               + sP[rl[i] * 4 + 2] + sP[rl[i] * 4 + 3]) * 0.0078125f;
    __syncthreads();
    float q[4];
#pragma unroll
    for (int i = 0; i < 4; i++) {
        float v = 0.f;
#pragma unroll
        for (int j = 0; j < 8; j++) {
            xx[i][j] -= mu[i];
            v += xx[i][j] * xx[i][j];
        }
        quadred(v);
        q[i] = v;
    }
    if (t4 == 0)
#pragma unroll
        for (int i = 0; i < 4; i++) sP[rl[i] * 4 + cq] = q[i];
    __syncthreads();
#pragma unroll
    for (int i = 0; i < 4; i++) {
        float rs = rsqrtf((sP[rl[i] * 4] + sP[rl[i] * 4 + 1]
                         + sP[rl[i] * 4 + 2] + sP[rl[i] * 4 + 3])
                          * 0.0078125f + 1e-5f);
#pragma unroll
        for (int n8 = 0; n8 < 4; n8++) {
            float2 gv = __ldg((const float2*)(gamma + cb + n8 * 8));
            float2 bv = __ldg((const float2*)(beta  + cb + n8 * 8));
            xx[i][2 * n8]     = xx[i][2 * n8]     * rs * gv.x + bv.x;
            xx[i][2 * n8 + 1] = xx[i][2 * n8 + 1] * rs * gv.y + bv.y;
        }
    }
}

__global__ __launch_bounds__(THREADS, 1) void treelstm_mma(
    const float* __restrict__ emb,  const float* __restrict__ h_child,
    const float* __restrict__ c_child, const int* __restrict__ n_type,
    const float* __restrict__ W_iou, const float* __restrict__ U_iou,
    const float* __restrict__ b_iou, const float* __restrict__ W_f,
    const float* __restrict__ U_f,   const float* __restrict__ b_f,
    const float* __restrict__ g_i,  const float* __restrict__ b_i,
    const float* __restrict__ g_o,  const float* __restrict__ b_o,
    const float* __restrict__ g_u,  const float* __restrict__ b_u,
    const float* __restrict__ gn_f, const float* __restrict__ bn_f,
    const float* __restrict__ gn_c, const float* __restrict__ bn_c,
    float* __restrict__ out, int n)
{
    extern __shared__ uint32_t sm[];
    uint32_t* sA = sm;
    char*     sAp = (char*)sm;
    char*     sBp = (char*)(sm + OFF_B);
    float*    sP = (float*)(sm + OFF_P);

    const int tid = threadIdx.x;
    const int lane = tid & 31, warp = tid >> 5;
    const int t4 = lane & 3, g = lane >> 2;
    const int rg = warp & 3, cq = warp >> 2;
    const int cb = cq * 32 + t4 * 2;
    const int c_ = tid >> 2, k8s = tid & 3;
    const int row0 = blockIdx.x * 128;
    const int rl[4] = { rg * 32 + g, rg * 32 + g + 8,
                        rg * 32 + g + 16, rg * 32 + g + 24 };

    // ---- Phase 0: pack A = [emb | ht0 | ht1] into fragment layout ----
    for (int e = tid; e < 128 * 32; e += THREADS) {
        int r = e >> 5, k4 = (e & 31) * 4;
        float4 v = __ldg((const float4*)(emb + (size_t)(row0 + r) * 128 + k4));
        storeA(sA, r, k4 + 0, v.x);
        storeA(sA, r, k4 + 1, v.y);
        storeA(sA, r, k4 + 2, v.z);
        storeA(sA, r, k4 + 3, v.w);
    }
    for (int e = tid; e < 128 * 128; e += THREADS) {
        int r = e >> 7, c = e & 127;
        const float* hp = h_child + ((size_t)(row0 + r) * 4) * 128 + c;
        float h0 = 0.f, h1 = 0.f;
#pragma unroll
        for (int k = 0; k < 4; k++) {
            float v = __ldg(hp + k * 128);
            if (__ldg(n_type + (size_t)(row0 + r) * 4 + k) == 0) h0 += v; else h1 += v;
        }
        storeA(sA, r, 128 + c, h0);
        storeA(sA, r, 256 + c, h1);
    }
    __syncthreads();

    float acc[2][4][4], X[2][4][4], cS[4][8], xx[4][8];
    int gc = 0;

#define ZACC()                                                \
    _Pragma("unroll") for (int m = 0; m < 2; m++)             \
    _Pragma("unroll") for (int n8 = 0; n8 < 4; n8++)          \
    _Pragma("unroll") for (int q = 0; q < 4; q++) acc[m][n8][q] = 0.f;

#define GATHER(BIAS)                                                   \
    _Pragma("unroll") for (int n8 = 0; n8 < 4; n8++) {                 \
        float2 bv = __ldg((const float2*)((BIAS) + cb + n8 * 8));      \
        xx[0][2*n8]   = acc[0][n8][0] + bv.x;                          \
        xx[0][2*n8+1] = acc[0][n8][1] + bv.y;                          \
        xx[1][2*n8]   = acc[0][n8][2] + bv.x;                          \
        xx[1][2*n8+1] = acc[0][n8][3] + bv.y;                          \
        xx[2][2*n8]   = acc[1][n8][0] + bv.x;                          \
        xx[2][2*n8+1] = acc[1][n8][1] + bv.y;                          \
        xx[3][2*n8]   = acc[1][n8][2] + bv.x;                          \
        xx[3][2*n8+1] = acc[1][n8][3] + bv.y;                          \
    }

    // ---- Gate u: cS = tanh(LN(u)) ----
    ZACC();
    run_gate(acc, W_iou + 256 * 128, U_iou + 256 * 256, sAp, sBp, gc, 0, 12,
             c_, k8s, rg, cq, lane);
    GATHER(b_iou + 256);
    ln4(xx, sP, rl, cq, t4, g_u, b_u, cb);
#pragma unroll
    for (int i = 0; i < 4; i++)
#pragma unroll
        for (int j = 0; j < 8; j++) cS[i][j] = tanhf(xx[i][j]);

    // ---- Gate i: cS *= sigm(LN(i)) ----
    ZACC();
    run_gate(acc, W_iou, U_iou, sAp, sBp, gc, 0, 12, c_, k8s, rg, cq, lane);
    GATHER(b_iou);
    ln4(xx, sP, rl, cq, t4, g_i, b_i, cb);
#pragma unroll
    for (int i = 0; i < 4; i++)
#pragma unroll
        for (int j = 0; j < 8; j++) cS[i][j] *= sigm(xx[i][j]);

    // ---- Gate f0: X = W_f*emb (shared); f0 = X + U_f0*hio ----
    ZACC();
    run_gate(acc, W_f, U_f, sAp, sBp, gc, 0, 4, c_, k8s, rg, cq, lane);
#pragma unroll
    for (int m = 0; m < 2; m++)
#pragma unroll
        for (int n8 = 0; n8 < 4; n8++)
#pragma unroll
            for (int q = 0; q < 4; q++) X[m][n8][q] = acc[m][n8][q];
    run_gate(acc, W_f, U_f, sAp, sBp, gc, 4, 12, c_, k8s, rg, cq, lane);
#pragma unroll 1
    for (int ft = 0; ft < 2; ft++) {
        GATHER(b_f);
        ln4(xx, sP, rl, cq, t4, gn_f, bn_f, cb);
#pragma unroll
        for (int i = 0; i < 4; i++) {
            size_t grow = (size_t)(row0 + rl[i]);
            int4 nt = __ldg((const int4*)(n_type + grow * 4));
            int ntk[4] = { nt.x, nt.y, nt.z, nt.w };
            float ct[8] = { 0.f, 0.f, 0.f, 0.f, 0.f, 0.f, 0.f, 0.f };
#pragma unroll
            for (int k = 0; k < 4; k++) {
                if (ntk[k] == ft) {
                    const float* cp = c_child + grow * 512 + k * 128 + cb;
#pragma unroll
                    for (int n8 = 0; n8 < 4; n8++) {
                        float2 v = __ldg((const float2*)(cp + n8 * 8));
                        ct[2 * n8] += v.x; ct[2 * n8 + 1] += v.y;
                    }
                }
            }
#pragma unroll
            for (int j = 0; j < 8; j++) cS[i][j] += sigm(xx[i][j]) * ct[j];
        }
        if (ft == 0) {
#pragma unroll
            for (int m = 0; m < 2; m++)
#pragma unroll
                for (int n8 = 0; n8 < 4; n8++)
#pragma unroll
                    for (int q = 0; q < 4; q++) acc[m][n8][q] = X[m][n8][q];
            run_gate(acc, W_f, U_f + 128 * 256, sAp, sBp, gc, 4, 12,
                     c_, k8s, rg, cq, lane);
        }
    }

    // ---- write c; cS := tanh(LN(c)) ----
#pragma unroll
    for (int i = 0; i < 4; i++) {
        float* oc = out + (size_t)n * 128 + (size_t)(row0 + rl[i]) * 128 + cb;
#pragma unroll
        for (int n8 = 0; n8 < 4; n8++) {
            *(float2*)(oc + n8 * 8) = make_float2(cS[i][2*n8], cS[i][2*n8+1]);
            xx[i][2*n8] = cS[i][2*n8]; xx[i][2*n8+1] = cS[i][2*n8+1];
        }
    }
    ln4(xx, sP, rl, cq, t4, gn_c, bn_c, cb);
#pragma unroll
    for (int i = 0; i < 4; i++)
#pragma unroll
        for (int j = 0; j < 8; j++) cS[i][j] = tanhf(xx[i][j]);

    // ---- Gate o: h = sigm(LN(o)) * tanh(LN(c)) ----
    ZACC();
    run_gate(acc, W_iou + 128 * 128, U_iou + 128 * 256, sAp, sBp, gc, 0, 12,
             c_, k8s, rg, cq, lane);
    GATHER(b_iou + 128);
    ln4(xx, sP, rl, cq, t4, g_o, b_o, cb);
#pragma unroll
    for (int i = 0; i < 4; i++) {
        float* oh = out + (size_t)(row0 + rl[i]) * 128 + cb;
#pragma unroll
        for (int n8 = 0; n8 < 4; n8++)
            *(float2*)(oh + n8 * 8) = make_float2(sigm(xx[i][2*n8])   * cS[i][2*n8],
                                                  sigm(xx[i][2*n8+1]) * cS[i][2*n8+1]);
    }
#undef GATHER
#undef ZACC
}

extern "C" void kernel_launch(void* const* d_in, const int* in_sizes, int n_in,
                              void* d_out, int out_size)
{
    const float* emb     = (const float*)d_in[0];
    const float* h_child = (const float*)d_in[1];
    const float* c_child = (const float*)d_in[2];
    const int*   n_type  = (const int*)  d_in[3];
    const float* W_iou   = (const float*)d_in[4];
    const float* U_iou   = (const float*)d_in[5];
    const float* b_iou   = (const float*)d_in[6];
    const float* W_f     = (const float*)d_in[7];
    const float* U_f     = (const float*)d_in[8];
    const float* b_f     = (const float*)d_in[9];
    const float* g_i  = (const float*)d_in[10];
    const float* b_i  = (const float*)d_in[11];
    const float* g_o  = (const float*)d_in[12];
    const float* b_o  = (const float*)d_in[13];
    const float* g_u  = (const float*)d_in[14];
    const float* b_u  = (const float*)d_in[15];
    const float* gn_f = (const float*)d_in[16];
    const float* bn_f = (const float*)d_in[17];
    const float* gn_c = (const float*)d_in[18];
    const float* bn_c = (const float*)d_in[19];
    float* out = (float*)d_out;

    int n = in_sizes[0] / 128;

    static int smem_set = 0;
    if (!smem_set) {
        cudaFuncSetAttribute(treelstm_mma,
                             cudaFuncAttributeMaxDynamicSharedMemorySize,
                             SMEM_BYTES);
        smem_set = 1;
    }

    treelstm_mma<<<n / 128, THREADS, SMEM_BYTES>>>(
        emb, h_child, c_child, n_type, W_iou, U_iou, b_iou, W_f, U_f, b_f,
        g_i, b_i, g_o, b_o, g_u, b_u, gn_f, bn_f, gn_c, bn_c, out, n);
}